// round 2
// baseline (speedup 1.0000x reference)
#include <cuda_runtime.h>
#include <math.h>

#define KSEL   20
#define CAP    2048
#define M_OUT  180
#define ROWB   (M_OUT * 8)

__device__ __forceinline__ bool better(float va, int ka, float vb, int kb) {
    return (va > vb) || (va == vb && ka < kb);
}

__global__ __launch_bounds__(512)
void detpost_kernel(const float* __restrict__ cls0, const float* __restrict__ shp0, const float* __restrict__ off0,
                    const float* __restrict__ cls1, const float* __restrict__ shp1, const float* __restrict__ off1,
                    const float* __restrict__ cls2, const float* __restrict__ shp2, const float* __restrict__ off2,
                    float* __restrict__ out)
{
    const int b   = blockIdx.x;
    const int tid = threadIdx.x;
    const int nthr = blockDim.x;

    __shared__ float s_v[CAP];
    __shared__ int   s_key[CAP];
    __shared__ int   s_cnt;
    __shared__ int   s_cntl[3];
    __shared__ float sel_s[KSEL];
    __shared__ int   sel_key[KSEL];
    __shared__ float s_box[KSEL][6];
    __shared__ float s_score[KSEL];
    __shared__ int   s_valid[KSEL];
    __shared__ float s_iou[KSEL * KSEL];
    __shared__ int   s_rowof[KSEL];
    __shared__ int   s_count;

    const float* clsp[3] = {cls0, cls1, cls2};
    const int    Ns[3]   = {32768, 4096, 512};
    // Logit-space pre-filter thresholds for N(0,1) cls; target E[survivors] ~ 100-150/level.
    float T[3] = {2.6f, 1.9f, 1.0f};

    // ---- Phase 1: threshold scan with deterministic fallback ----
    for (int attempt = 0; attempt < 32; attempt++) {
        if (tid == 0) { s_cnt = 0; s_cntl[0] = 0; s_cntl[1] = 0; s_cntl[2] = 0; }
        __syncthreads();
        #pragma unroll
        for (int l = 0; l < 3; l++) {
            const int N = Ns[l];
            const float4* p = (const float4*)(clsp[l] + (size_t)b * N);
            const float Tl = T[l];
            for (int i4 = tid; i4 < (N >> 2); i4 += nthr) {
                float4 v = p[i4];
                float vv[4] = {v.x, v.y, v.z, v.w};
                #pragma unroll
                for (int c = 0; c < 4; c++) {
                    if (vv[c] > Tl) {
                        atomicAdd(&s_cntl[l], 1);
                        int pos = atomicAdd(&s_cnt, 1);
                        if (pos < CAP) { s_v[pos] = vv[c]; s_key[pos] = (l << 16) | (i4 * 4 + c); }
                    }
                }
            }
        }
        __syncthreads();
        bool ok = (s_cnt <= CAP) && (s_cntl[0] >= KSEL) && (s_cntl[1] >= KSEL) && (s_cntl[2] >= KSEL);
        if (ok) break;
        #pragma unroll
        for (int l = 0; l < 3; l++) {
            if (s_cntl[l] < KSEL) T[l] -= 0.75f;
            else if (s_cnt > CAP && s_cntl[l] > 4 * KSEL) T[l] += 0.5f;
        }
        __syncthreads();
    }

    const int total = min(s_cnt, CAP);

    // Convert survivor logits -> sigmoid scores (match reference tie semantics on scores).
    for (int i = tid; i < total; i += nthr)
        s_v[i] = 1.0f / (1.0f + expf(-s_v[i]));
    __syncthreads();

    // ---- Warps 1..15: fill rows 20..179 with -1 (disjoint from warp 0's rows) ----
    if (tid >= 32) {
        const int base = b * ROWB + KSEL * 8;
        for (int e = tid - 32; e < (M_OUT - KSEL) * 8; e += nthr - 32)
            out[base + e] = -1.0f;
        return;
    }

    // ---- Warp 0: exact global top-20 (score desc, level asc, idx asc) ----
    const int lane = tid;
    for (int k = 0; k < KSEL; k++) {
        float bv = -1e30f; int bk = 0x7fffffff; int bpos = -1;
        for (int j = lane; j < total; j += 32) {
            float v = s_v[j]; int key = s_key[j];
            if (better(v, key, bv, bk)) { bv = v; bk = key; bpos = j; }
        }
        #pragma unroll
        for (int o = 16; o >= 1; o >>= 1) {
            float ov = __shfl_down_sync(0xffffffffu, bv, o);
            int   ok2 = __shfl_down_sync(0xffffffffu, bk, o);
            int   op  = __shfl_down_sync(0xffffffffu, bpos, o);
            if (better(ov, ok2, bv, bk)) { bv = ov; bk = ok2; bpos = op; }
        }
        if (lane == 0) {
            if (bpos >= 0) { sel_s[k] = bv; sel_key[k] = bk; s_v[bpos] = -1e30f; }
            else           { sel_s[k] = -1e30f; sel_key[k] = 0; }
        }
        __syncwarp();
    }

    // ---- Gather + decode the 20 candidate boxes ----
    if (lane < KSEL) {
        int key = sel_key[lane];
        int l = key >> 16, idx = key & 0xffff;
        int S = (l == 0) ? 32 : ((l == 1) ? 16 : 8);
        int N = S * S * S;
        float stride = 128.0f / (float)S;
        int z = idx / (S * S);
        int rem = idx - z * S * S;
        int y = rem / S;
        int x = rem - y * S;
        const float* shp = (l == 0) ? shp0 : ((l == 1) ? shp1 : shp2);
        const float* off = (l == 0) ? off0 : ((l == 1) ? off1 : off2);
        size_t base = (size_t)b * 3 * N;
        float cz = ((float)z + off[base + 0 * (size_t)N + idx]) * stride;
        float cy = ((float)y + off[base + 1 * (size_t)N + idx]) * stride;
        float cx = ((float)x + off[base + 2 * (size_t)N + idx]) * stride;
        s_box[lane][0] = cz;
        s_box[lane][1] = cy;
        s_box[lane][2] = cx;
        s_box[lane][3] = shp[base + 0 * (size_t)N + idx];
        s_box[lane][4] = shp[base + 1 * (size_t)N + idx];
        s_box[lane][5] = shp[base + 2 * (size_t)N + idx];
        float sc = sel_s[lane];
        s_score[lane] = sc;
        s_valid[lane] = (sc > 0.15f) ? 1 : 0;
    }
    __syncwarp();

    // ---- Pairwise 3D IoU (lower triangle) ----
    for (int p = lane; p < KSEL * KSEL; p += 32) {
        int i = p / KSEL, j = p % KSEL;
        if (j < i) {
            float inter = 1.0f, voli = 1.0f, volj = 1.0f;
            #pragma unroll
            for (int d = 0; d < 3; d++) {
                float ci = s_box[i][d],      cj = s_box[j][d];
                float si = fmaxf(s_box[i][3 + d], 0.0f);
                float sj = fmaxf(s_box[j][3 + d], 0.0f);
                float loi = ci - 0.5f * si, hii = ci + 0.5f * si;
                float loj = cj - 0.5f * sj, hij = cj + 0.5f * sj;
                float w = fminf(hii, hij) - fmaxf(loi, loj);
                inter *= fmaxf(w, 0.0f);
                voli *= si; volj *= sj;
            }
            s_iou[p] = inter / (voli + volj - inter + 1e-8f);
        }
    }
    __syncwarp();

    // ---- Greedy NMS (serial, lane 0) ----
    if (lane == 0) {
        unsigned kept = 0; int cnt = 0;
        for (int i = 0; i < KSEL; i++) {
            bool sup = false;
            for (int j = 0; j < i; j++)
                if (((kept >> j) & 1u) && s_iou[i * KSEL + j] > 0.05f) sup = true;
            bool kp = (s_valid[i] != 0) && !sup;
            if (kp) kept |= (1u << i);
            s_rowof[i] = kp ? cnt++ : -1;
        }
        s_count = cnt;
    }
    __syncwarp();

    // ---- Write kept rows + fill remaining rows [count,20) with -1 ----
    if (lane < KSEL) {
        int r = s_rowof[lane];
        if (r >= 0) {
            float* o = out + (size_t)b * ROWB + (size_t)r * 8;
            o[0] = 1.0f;
            o[1] = s_score[lane];
            o[2] = s_box[lane][0];
            o[3] = s_box[lane][1];
            o[4] = s_box[lane][2];
            o[5] = s_box[lane][3];
            o[6] = s_box[lane][4];
            o[7] = s_box[lane][5];
        }
    }
    {
        int cnt = s_count;
        for (int r = cnt + lane; r < KSEL; r += 32) {
            float* o = out + (size_t)b * ROWB + (size_t)r * 8;
            #pragma unroll
            for (int e = 0; e < 8; e++) o[e] = -1.0f;
        }
    }
}

extern "C" void kernel_launch(void* const* d_in, const int* in_sizes, int n_in,
                              void* d_out, int out_size) {
    detpost_kernel<<<64, 512>>>(
        (const float*)d_in[0], (const float*)d_in[1], (const float*)d_in[2],
        (const float*)d_in[3], (const float*)d_in[4], (const float*)d_in[5],
        (const float*)d_in[6], (const float*)d_in[7], (const float*)d_in[8],
        (float*)d_out);
}